// round 1
// baseline (speedup 1.0000x reference)
#include <cuda_runtime.h>
#include <cuda_bf16.h>
#include <math.h>

// Problem constants
#define BATCH 2
#define CDIM  192
#define C3    576
#define HDIM  256
#define WDIM  256
#define HWSZ  (HDIM*WDIM)       // 65536
#define HEADS 6
#define CHD   32
#define WS    8
#define NTOK  64
#define H1    32
#define NWIN  (BATCH*H1*H1)     // 2048
#define KD    192               // K dim for both GEMMs

// Scratch (device globals; no allocation allowed)
__device__ float g_qkv[(size_t)BATCH*C3*HWSZ];    // 302 MB
__device__ float g_dw [(size_t)BATCH*C3*HWSZ];    // 302 MB
__device__ float g_t  [(size_t)BATCH*CDIM*HWSZ];  // 100 MB
__device__ float g_wt_qkv[KD*C3];                 // transposed qkv weights [k][m]
__device__ float g_wt_proj[KD*CDIM];              // transposed proj weights [k][m]

// ---------------------------------------------------------------------------
// K0: transpose weights [M,K] -> [K,M] for coalesced GEMM A loads
// ---------------------------------------------------------------------------
__global__ void k_transpose(const float* __restrict__ w, float* __restrict__ wt,
                            int M, int K)
{
    int i = blockIdx.x * 256 + threadIdx.x;
    if (i < M * K) {
        int m = i / K, k = i % K;
        wt[k * M + m] = w[i];
    }
}

// ---------------------------------------------------------------------------
// K1/K4: GEMM  Y[b,m,hw] = sum_k WT[k,m] * X[b,k,hw] (+ bias[m])
// Tile: 64 (M) x 128 (N pixels), K staged 16 at a time. 256 threads,
// each thread computes a 4x8 register tile.
// ---------------------------------------------------------------------------
__global__ __launch_bounds__(256) void k_gemm(
    const float* __restrict__ WT,   // [KD][Mtot]
    const float* __restrict__ X,    // [BATCH][KD][HWSZ]
    float* __restrict__ Y,          // [BATCH][Mtot][HWSZ]
    const float* __restrict__ bias, int hasBias, int Mtot)
{
    __shared__ float As[16 * 64];    // [kk][m]
    __shared__ float Bs[16 * 128];   // [kk][col]

    int tid = threadIdx.x;
    int m0  = blockIdx.y * 64;
    int pt  = blockIdx.x;                    // pixel tile (128 px); HWSZ%128==0
    int b   = (pt * 128) / HWSZ;
    int hw0 = pt * 128 - b * HWSZ;
    const float* Xb = X + (size_t)b * KD * HWSZ + hw0;

    int tm = tid >> 4;       // 0..15 -> M rows (x4)
    int tn = tid & 15;       // 0..15 -> N cols (x4, two halves)

    float acc[4][8];
    #pragma unroll
    for (int i = 0; i < 4; i++)
        #pragma unroll
        for (int j = 0; j < 8; j++) acc[i][j] = 0.f;

    for (int k0 = 0; k0 < KD; k0 += 16) {
        __syncthreads();
        // A chunk: 16x64, coalesced from transposed weights
        #pragma unroll
        for (int i = tid; i < 1024; i += 256) {
            int kk = i >> 6, m = i & 63;
            As[i] = WT[(size_t)(k0 + kk) * Mtot + m0 + m];
        }
        // B chunk: 16x128 via float4 (HW-contiguous, aligned)
        #pragma unroll
        for (int i = tid; i < 512; i += 256) {
            int kk = i >> 5, c4 = (i & 31) << 2;
            *(float4*)(Bs + kk * 128 + c4) =
                *(const float4*)(Xb + (size_t)(k0 + kk) * HWSZ + c4);
        }
        __syncthreads();

        #pragma unroll
        for (int kk = 0; kk < 16; ++kk) {
            const float* Ar = As + kk * 64 + tm * 4;
            const float* Br = Bs + kk * 128 + tn * 4;
            float a0 = Ar[0], a1 = Ar[1], a2 = Ar[2], a3 = Ar[3];
            float4 bA = *(const float4*)Br;
            float4 bB = *(const float4*)(Br + 64);
            acc[0][0] += a0*bA.x; acc[0][1] += a0*bA.y; acc[0][2] += a0*bA.z; acc[0][3] += a0*bA.w;
            acc[0][4] += a0*bB.x; acc[0][5] += a0*bB.y; acc[0][6] += a0*bB.z; acc[0][7] += a0*bB.w;
            acc[1][0] += a1*bA.x; acc[1][1] += a1*bA.y; acc[1][2] += a1*bA.z; acc[1][3] += a1*bA.w;
            acc[1][4] += a1*bB.x; acc[1][5] += a1*bB.y; acc[1][6] += a1*bB.z; acc[1][7] += a1*bB.w;
            acc[2][0] += a2*bA.x; acc[2][1] += a2*bA.y; acc[2][2] += a2*bA.z; acc[2][3] += a2*bA.w;
            acc[2][4] += a2*bB.x; acc[2][5] += a2*bB.y; acc[2][6] += a2*bB.z; acc[2][7] += a2*bB.w;
            acc[3][0] += a3*bA.x; acc[3][1] += a3*bA.y; acc[3][2] += a3*bA.z; acc[3][3] += a3*bA.w;
            acc[3][4] += a3*bB.x; acc[3][5] += a3*bB.y; acc[3][6] += a3*bB.z; acc[3][7] += a3*bB.w;
        }
    }

    #pragma unroll
    for (int i = 0; i < 4; i++) {
        int m = m0 + tm * 4 + i;
        float bv = hasBias ? bias[m] : 0.f;
        float* dst = Y + ((size_t)b * Mtot + m) * HWSZ + hw0;
        float4 o1 = make_float4(acc[i][0]+bv, acc[i][1]+bv, acc[i][2]+bv, acc[i][3]+bv);
        float4 o2 = make_float4(acc[i][4]+bv, acc[i][5]+bv, acc[i][6]+bv, acc[i][7]+bv);
        *(float4*)(dst + tn * 4)      = o1;
        *(float4*)(dst + 64 + tn * 4) = o2;
    }
}

// ---------------------------------------------------------------------------
// K2: depthwise 3x3 conv, zero pad 1. One block per (y, ch, b), 256 threads=x.
// ---------------------------------------------------------------------------
__global__ __launch_bounds__(256) void k_dw(const float* __restrict__ w_dw)
{
    int y  = blockIdx.x;
    int ch = blockIdx.y;
    int b  = blockIdx.z;
    int x  = threadIdx.x;

    const float* wk = w_dw + ch * 9;
    float w00=wk[0], w01=wk[1], w02=wk[2];
    float w10=wk[3], w11=wk[4], w12=wk[5];
    float w20=wk[6], w21=wk[7], w22=wk[8];

    size_t base = ((size_t)b * C3 + ch) * HWSZ;
    float acc = 0.f;

    #pragma unroll
    for (int dy = -1; dy <= 1; dy++) {
        int yy = y + dy;
        if (yy < 0 || yy >= HDIM) continue;
        const float* row = g_qkv + base + (size_t)yy * WDIM;
        float wl = (dy==-1) ? w00 : (dy==0 ? w10 : w20);
        float wc = (dy==-1) ? w01 : (dy==0 ? w11 : w21);
        float wr = (dy==-1) ? w02 : (dy==0 ? w12 : w22);
        if (x > 0)        acc += wl * row[x - 1];
        acc += wc * row[x];
        if (x < WDIM - 1) acc += wr * row[x + 1];
    }
    g_dw[base + (size_t)y * WDIM + x] = acc;
}

// ---------------------------------------------------------------------------
// K3: fused windowed channel attention per (window, head).
//   load q/k/v (32x64 each) -> l2norm(q,k) -> attn = softmax(q k^T * temp)
//   -> out = attn v ;  gate = GELU(v @ mlp_w^T + b) ; out *= gate -> g_t
// 128 threads per block; grid (2048, 6).
// ---------------------------------------------------------------------------
__global__ __launch_bounds__(128) void k_attn(
    const float* __restrict__ temp,
    const float* __restrict__ mlp_w,
    const float* __restrict__ mlp_b)
{
    __shared__ float sq[32 * 65];
    __shared__ float sk[32 * 65];
    __shared__ float sv[32 * 65];
    __shared__ float satt[32 * 33];
    __shared__ float sml[64 * 65];
    __shared__ float sb[64];

    int tid  = threadIdx.x;
    int wi   = blockIdx.x;       // window index
    int head = blockIdx.y;
    int b  = wi >> 10;
    int r  = wi & 1023;
    int h1 = r >> 5, w1 = r & 31;

    float tscale = temp[head];

    // --- load q/k/v tiles (32 ch x 64 tok each), float4 global reads ---
    for (int i = tid; i < 1536; i += 128) {
        int z = i / 512;             // 0=q 1=k 2=v
        int rr = i - z * 512;
        int c  = rr >> 4;            // channel 0..31
        int q8 = rr & 15;
        int ty = q8 >> 1, half = q8 & 1;
        const float* gp = g_dw +
            (((size_t)(b * C3 + z * CDIM + head * CHD + c)) * HDIM + (h1*8 + ty)) * WDIM
            + w1 * 8 + half * 4;
        float4 v = *(const float4*)gp;
        float* s = (z == 0 ? sq : (z == 1 ? sk : sv)) + c * 65 + ty * 8 + half * 4;
        s[0] = v.x; s[1] = v.y; s[2] = v.z; s[3] = v.w;
    }
    // mlp weights + bias
    for (int i = tid; i < 4096; i += 128)
        sml[(i >> 6) * 65 + (i & 63)] = mlp_w[i];
    if (tid < 64) sb[tid] = mlp_b[tid];
    __syncthreads();

    // --- l2 normalize q and k rows (over 64 tokens) ---
    if (tid < 64) {
        float* row = (tid < 32) ? (sq + tid * 65) : (sk + (tid - 32) * 65);
        float s = 0.f;
        #pragma unroll
        for (int t = 0; t < 64; t++) s += row[t] * row[t];
        float n = fmaxf(sqrtf(s), 1e-12f);
        float inv = 1.f / n;
        #pragma unroll
        for (int t = 0; t < 64; t++) row[t] *= inv;
    }
    __syncthreads();

    // --- attn[c][d] = (q_c . k_d) * temperature ---
    #pragma unroll
    for (int i = 0; i < 8; i++) {
        int e = tid + i * 128;               // 0..1023
        int c = e >> 5, d = e & 31;
        const float* qr = sq + c * 65;
        const float* kr = sk + d * 65;
        float s = 0.f;
        #pragma unroll
        for (int t = 0; t < 64; t++) s += qr[t] * kr[t];
        satt[c * 33 + d] = s * tscale;
    }
    __syncthreads();

    // --- softmax over d (row-wise, stable) ---
    if (tid < 32) {
        float* rr = satt + tid * 33;
        float mx = rr[0];
        #pragma unroll
        for (int d = 1; d < 32; d++) mx = fmaxf(mx, rr[d]);
        float s = 0.f;
        #pragma unroll
        for (int d = 0; d < 32; d++) { float ev = __expf(rr[d] - mx); rr[d] = ev; s += ev; }
        float inv = 1.f / s;
        #pragma unroll
        for (int d = 0; d < 32; d++) rr[d] *= inv;
    }
    __syncthreads();

    // --- out[c][t] = sum_d attn[c][d] v[d][t];  gate = GELU(v[c]·mlp_w[t] + b[t]) ---
    #pragma unroll
    for (int i = 0; i < 16; i++) {
        int e = tid + i * 128;               // 0..2047
        int c = e >> 6, t = e & 63;
        const float* ar = satt + c * 33;
        float ov = 0.f;
        #pragma unroll
        for (int d = 0; d < 32; d++) ov += ar[d] * sv[d * 65 + t];
        const float* vr = sv + c * 65;
        const float* mr = sml + t * 65;
        float gv = sb[t];
        #pragma unroll
        for (int x = 0; x < 64; x++) gv += vr[x] * mr[x];
        // exact GELU: 0.5*x*(1+erf(x/sqrt(2)))
        float gl = 0.5f * gv * (1.f + erff(gv * 0.70710678118654752f));
        float res = ov * gl;
        g_t[(((size_t)(b * CDIM + head * CHD + c)) * HDIM + (h1*8 + (t >> 3))) * WDIM
            + w1 * 8 + (t & 7)] = res;
    }
}

// ---------------------------------------------------------------------------
extern "C" void kernel_launch(void* const* d_in, const int* in_sizes, int n_in,
                              void* d_out, int out_size)
{
    const float* x      = (const float*)d_in[0];
    const float* w_qkv  = (const float*)d_in[1];
    const float* w_dw   = (const float*)d_in[2];
    const float* temp   = (const float*)d_in[3];
    const float* mlp_w  = (const float*)d_in[4];
    const float* mlp_b  = (const float*)d_in[5];
    const float* proj_w = (const float*)d_in[6];
    const float* proj_b = (const float*)d_in[7];
    float* out = (float*)d_out;
    (void)in_sizes; (void)n_in; (void)out_size;

    float *p_qkv, *p_dw, *p_t, *p_wtq, *p_wtp;
    cudaGetSymbolAddress((void**)&p_qkv, g_qkv);
    cudaGetSymbolAddress((void**)&p_dw,  g_dw);
    cudaGetSymbolAddress((void**)&p_t,   g_t);
    cudaGetSymbolAddress((void**)&p_wtq, g_wt_qkv);
    cudaGetSymbolAddress((void**)&p_wtp, g_wt_proj);
    (void)p_dw;

    // K0: transpose both weight matrices
    k_transpose<<<(C3*KD + 255)/256, 256>>>(w_qkv, p_wtq, C3, KD);
    k_transpose<<<(CDIM*KD + 255)/256, 256>>>(proj_w, p_wtp, CDIM, KD);

    // K1: qkv = W_qkv @ x  (M=576, N=131072, K=192)
    k_gemm<<<dim3(BATCH*HWSZ/128, C3/64), 256>>>(p_wtq, x, p_qkv, nullptr, 0, C3);

    // K2: depthwise 3x3
    k_dw<<<dim3(HDIM, C3, BATCH), 256>>>(w_dw);

    // K3: windowed channel attention + gate
    k_attn<<<dim3(NWIN, HEADS), 128>>>(temp, mlp_w, mlp_b);

    // K4: projection (M=192, K=192) + bias -> d_out
    k_gemm<<<dim3(BATCH*HWSZ/128, CDIM/64), 256>>>(p_wtp, p_t, out, proj_b, 1, CDIM);
}

// round 3
// speedup vs baseline: 1.3026x; 1.3026x over previous
#include <cuda_runtime.h>
#include <cuda_bf16.h>
#include <math.h>

// Problem constants
#define BATCH 2
#define CDIM  192
#define C3    576
#define HDIM  256
#define WDIM  256
#define HWSZ  (HDIM*WDIM)       // 65536
#define HEADS 6
#define CHD   32
#define WS    8
#define NTOK  64
#define H1    32
#define NWIN  (BATCH*H1*H1)     // 2048
#define KD    192

typedef unsigned long long u64;

// packed f32x2 helpers (SASS FFMA2 path — only reachable via PTX)
__device__ __forceinline__ u64 pk1(float x) {
    u64 r; asm("mov.b64 %0,{%1,%1};" : "=l"(r) : "f"(x)); return r;
}
__device__ __forceinline__ u64 pk2(float x, float y) {
    u64 r; asm("mov.b64 %0,{%1,%2};" : "=l"(r) : "f"(x), "f"(y)); return r;
}
__device__ __forceinline__ void fma2(u64& d, u64 a, u64 b) {
    asm("fma.rn.f32x2 %0,%1,%2,%3;" : "=l"(d) : "l"(a), "l"(b), "l"(d));
}
__device__ __forceinline__ void mul2(u64& d, u64 a, u64 b) {
    asm("mul.rn.f32x2 %0,%1,%2;" : "=l"(d) : "l"(a), "l"(b));
}
__device__ __forceinline__ float2 up2(u64 v) {
    float2 f; asm("mov.b64 {%0,%1},%2;" : "=f"(f.x), "=f"(f.y) : "l"(v)); return f;
}

// Scratch (device globals; no allocation allowed)
__device__ float g_qkv[(size_t)BATCH*C3*HWSZ];
__device__ float g_dw [(size_t)BATCH*C3*HWSZ];
__device__ float g_t  [(size_t)BATCH*CDIM*HWSZ];
__device__ float g_wt_qkv[KD*C3];
__device__ float g_wt_proj[KD*CDIM];

// ---------------------------------------------------------------------------
// K0: transpose weights [M,K] -> [K,M]
// ---------------------------------------------------------------------------
__global__ void k_transpose(const float* __restrict__ w, float* __restrict__ wt,
                            int M, int K)
{
    int i = blockIdx.x * 256 + threadIdx.x;
    if (i < M * K) {
        int m = i / K, k = i % K;
        wt[k * M + m] = w[i];
    }
}

// ---------------------------------------------------------------------------
// K1/K4: GEMM  Y[b,m,hw] = sum_k WT[k,m] * X[b,k,hw] (+ bias[m])
// Tile 64(M) x 128(N), 128 threads, 8x8 register tile per thread, FFMA2 math.
// ---------------------------------------------------------------------------
__global__ __launch_bounds__(128) void k_gemm(
    const float* __restrict__ WT,   // [KD][Mtot]
    const float* __restrict__ X,    // [BATCH][KD][HWSZ]
    float* __restrict__ Y,          // [BATCH][Mtot][HWSZ]
    const float* __restrict__ bias, int hasBias, int Mtot)
{
    __shared__ float As[16 * 64];    // [kk][m]
    __shared__ float Bs[16 * 128];   // [kk][col]

    int tid = threadIdx.x;
    int m0  = blockIdx.y * 64;
    int pt  = blockIdx.x;
    int b   = (pt * 128) / HWSZ;
    int hw0 = pt * 128 - b * HWSZ;
    const float* Xb = X + (size_t)b * KD * HWSZ + hw0;

    int tm = tid >> 4;       // 0..7 -> 8 M rows each
    int tn = tid & 15;       // 0..15 -> cols tn*4 and tn*4+64

    u64 acc[8][4];
    #pragma unroll
    for (int i = 0; i < 8; i++)
        #pragma unroll
        for (int j = 0; j < 4; j++) acc[i][j] = 0ull;

    for (int k0 = 0; k0 < KD; k0 += 16) {
        __syncthreads();
        #pragma unroll
        for (int i = tid; i < 1024; i += 128) {
            int kk = i >> 6, m = i & 63;
            As[i] = WT[(size_t)(k0 + kk) * Mtot + m0 + m];
        }
        #pragma unroll
        for (int i = tid; i < 512; i += 128) {
            int kk = i >> 5, c4 = (i & 31) << 2;
            *(float4*)(Bs + kk * 128 + c4) =
                *(const float4*)(Xb + (size_t)(k0 + kk) * HWSZ + c4);
        }
        __syncthreads();

        #pragma unroll
        for (int kk = 0; kk < 16; ++kk) {
            float4 a0 = *(const float4*)(As + kk * 64 + tm * 8);
            float4 a1 = *(const float4*)(As + kk * 64 + tm * 8 + 4);
            float4 bA = *(const float4*)(Bs + kk * 128 + tn * 4);
            float4 bB = *(const float4*)(Bs + kk * 128 + 64 + tn * 4);
            u64 b0 = pk2(bA.x, bA.y), b1 = pk2(bA.z, bA.w);
            u64 b2 = pk2(bB.x, bB.y), b3 = pk2(bB.z, bB.w);
            float ar[8] = {a0.x, a0.y, a0.z, a0.w, a1.x, a1.y, a1.z, a1.w};
            #pragma unroll
            for (int r = 0; r < 8; r++) {
                u64 ap = pk1(ar[r]);
                fma2(acc[r][0], ap, b0);
                fma2(acc[r][1], ap, b1);
                fma2(acc[r][2], ap, b2);
                fma2(acc[r][3], ap, b3);
            }
        }
    }

    #pragma unroll
    for (int r = 0; r < 8; r++) {
        int m = m0 + tm * 8 + r;
        float bv = hasBias ? bias[m] : 0.f;
        float2 p0 = up2(acc[r][0]), p1 = up2(acc[r][1]);
        float2 p2 = up2(acc[r][2]), p3 = up2(acc[r][3]);
        float* dst = Y + ((size_t)b * Mtot + m) * HWSZ + hw0;
        *(float4*)(dst + tn * 4)      = make_float4(p0.x+bv, p0.y+bv, p1.x+bv, p1.y+bv);
        *(float4*)(dst + 64 + tn * 4) = make_float4(p2.x+bv, p2.y+bv, p3.x+bv, p3.y+bv);
    }
}

// ---------------------------------------------------------------------------
// K2: depthwise 3x3, zero pad 1. float4 per thread (4 px). 128 thr = 2 rows.
// ---------------------------------------------------------------------------
__global__ __launch_bounds__(128) void k_dw(const float* __restrict__ w_dw)
{
    int tid = threadIdx.x;
    int ty = tid >> 6, tx = tid & 63;
    int y  = blockIdx.x * 2 + ty;
    int ch = blockIdx.y;
    int b  = blockIdx.z;
    int x0 = tx << 2;

    const float* wk = w_dw + ch * 9;
    size_t base = ((size_t)b * C3 + ch) * HWSZ;
    const float* src = g_qkv + base;

    float4 o = make_float4(0.f, 0.f, 0.f, 0.f);

    #pragma unroll
    for (int dy = -1; dy <= 1; dy++) {
        int yy = y + dy;
        if (yy < 0 || yy >= HDIM) continue;
        const float* row = src + (size_t)yy * WDIM + x0;
        float4 m = *(const float4*)row;
        float lft = (x0 > 0)   ? row[-1] : 0.f;
        float rgt = (x0 < 252) ? row[4]  : 0.f;
        float wl = wk[(dy+1)*3], wc = wk[(dy+1)*3+1], wr = wk[(dy+1)*3+2];
        o.x += wl*lft + wc*m.x + wr*m.y;
        o.y += wl*m.x + wc*m.y + wr*m.z;
        o.z += wl*m.y + wc*m.z + wr*m.w;
        o.w += wl*m.z + wc*m.w + wr*rgt;
    }
    *(float4*)(g_dw + base + (size_t)y * WDIM + x0) = o;
}

// ---------------------------------------------------------------------------
// K3: fused windowed channel attention per (window, head). f32x2 dots.
// smem row stride 66 (8B aligned, conflict-free for 64-bit phases).
// ---------------------------------------------------------------------------
__global__ __launch_bounds__(128) void k_attn(
    const float* __restrict__ temp,
    const float* __restrict__ mlp_w,
    const float* __restrict__ mlp_b)
{
    __shared__ float sq[32 * 66];
    __shared__ float sk[32 * 66];
    __shared__ float sv[32 * 66];
    __shared__ float satt[32 * 33];
    __shared__ float sml[64 * 66];
    __shared__ float sb[64];

    int tid  = threadIdx.x;
    int wi   = blockIdx.x;
    int head = blockIdx.y;
    int b  = wi >> 10;
    int r  = wi & 1023;
    int h1 = r >> 5, w1 = r & 31;

    float tscale = temp[head];

    // --- load q/k/v tiles (32 ch x 64 tok), float4 global reads ---
    for (int i = tid; i < 1536; i += 128) {
        int z = i / 512;
        int rr = i - z * 512;
        int c  = rr >> 4;
        int q8 = rr & 15;
        int ty = q8 >> 1, half = q8 & 1;
        const float* gp = g_dw +
            (((size_t)(b * C3 + z * CDIM + head * CHD + c)) * HDIM + (h1*8 + ty)) * WDIM
            + w1 * 8 + half * 4;
        float4 v = *(const float4*)gp;
        float* s = (z == 0 ? sq : (z == 1 ? sk : sv)) + c * 66 + ty * 8 + half * 4;
        s[0] = v.x; s[1] = v.y; s[2] = v.z; s[3] = v.w;
    }
    for (int i = tid; i < 4096; i += 128)
        sml[(i >> 6) * 66 + (i & 63)] = mlp_w[i];
    if (tid < 64) sb[tid] = mlp_b[tid];
    __syncthreads();

    // --- l2 normalize q and k rows ---
    if (tid < 64) {
        float* row = (tid < 32) ? (sq + tid * 66) : (sk + (tid - 32) * 66);
        u64 s2 = 0ull;
        #pragma unroll
        for (int t = 0; t < 64; t += 2) {
            u64 v = *(const u64*)(row + t);
            fma2(s2, v, v);
        }
        float2 sp = up2(s2);
        float n = fmaxf(sqrtf(sp.x + sp.y), 1e-12f);
        u64 inv = pk1(1.f / n);
        #pragma unroll
        for (int t = 0; t < 64; t += 2) {
            u64 v = *(const u64*)(row + t);
            mul2(v, v, inv);
            *(u64*)(row + t) = v;
        }
    }
    __syncthreads();

    // --- attn[c][d] = (q_c . k_d) * temperature ---
    #pragma unroll
    for (int i = 0; i < 8; i++) {
        int e = tid + i * 128;
        int c = e >> 5, d = e & 31;
        const float* qr = sq + c * 66;
        const float* kr = sk + d * 66;
        u64 s2 = 0ull;
        #pragma unroll
        for (int t = 0; t < 64; t += 2)
            fma2(s2, *(const u64*)(qr + t), *(const u64*)(kr + t));
        float2 sp = up2(s2);
        satt[c * 33 + d] = (sp.x + sp.y) * tscale;
    }
    __syncthreads();

    // --- softmax over d ---
    if (tid < 32) {
        float* rr = satt + tid * 33;
        float mx = rr[0];
        #pragma unroll
        for (int d = 1; d < 32; d++) mx = fmaxf(mx, rr[d]);
        float s = 0.f;
        #pragma unroll
        for (int d = 0; d < 32; d++) { float ev = __expf(rr[d] - mx); rr[d] = ev; s += ev; }
        float inv = 1.f / s;
        #pragma unroll
        for (int d = 0; d < 32; d++) rr[d] *= inv;
    }
    __syncthreads();

    // --- out[c][t] = attn.v ; gate = GELU(v[c]·mlp_w[t]+b[t]) ; out*=gate ---
    #pragma unroll
    for (int i = 0; i < 16; i++) {
        int e = tid + i * 128;
        int c = e >> 6, t = e & 63;
        const float* ar = satt + c * 33;
        float ov = 0.f;
        #pragma unroll
        for (int d = 0; d < 32; d++) ov += ar[d] * sv[d * 66 + t];
        const float* vr = sv + c * 66;
        const float* mr = sml + t * 66;
        u64 g2 = 0ull;
        #pragma unroll
        for (int x = 0; x < 64; x += 2)
            fma2(g2, *(const u64*)(vr + x), *(const u64*)(mr + x));
        float2 gp = up2(g2);
        float gv = sb[t] + gp.x + gp.y;
        float gl = 0.5f * gv * (1.f + erff(gv * 0.70710678118654752f));
        float res = ov * gl;
        g_t[(((size_t)(b * CDIM + head * CHD + c)) * HDIM + (h1*8 + (t >> 3))) * WDIM
            + w1 * 8 + (t & 7)] = res;
    }
}

// ---------------------------------------------------------------------------
extern "C" void kernel_launch(void* const* d_in, const int* in_sizes, int n_in,
                              void* d_out, int out_size)
{
    const float* x      = (const float*)d_in[0];
    const float* w_qkv  = (const float*)d_in[1];
    const float* w_dw   = (const float*)d_in[2];
    const float* temp   = (const float*)d_in[3];
    const float* mlp_w  = (const float*)d_in[4];
    const float* mlp_b  = (const float*)d_in[5];
    const float* proj_w = (const float*)d_in[6];
    const float* proj_b = (const float*)d_in[7];
    float* out = (float*)d_out;
    (void)in_sizes; (void)n_in; (void)out_size;

    float *p_wtq, *p_wtp;
    cudaGetSymbolAddress((void**)&p_wtq, g_wt_qkv);
    cudaGetSymbolAddress((void**)&p_wtp, g_wt_proj);
    float *p_qkv, *p_t;
    cudaGetSymbolAddress((void**)&p_qkv, g_qkv);
    cudaGetSymbolAddress((void**)&p_t,   g_t);

    k_transpose<<<(C3*KD + 255)/256, 256>>>(w_qkv, p_wtq, C3, KD);
    k_transpose<<<(CDIM*KD + 255)/256, 256>>>(proj_w, p_wtp, CDIM, KD);

    // K1: qkv = W_qkv @ x  (M=576, N=131072, K=192)
    k_gemm<<<dim3(BATCH*HWSZ/128, C3/64), 128>>>(p_wtq, x, p_qkv, nullptr, 0, C3);

    // K2: depthwise 3x3
    k_dw<<<dim3(HDIM/2, C3, BATCH), 128>>>(w_dw);

    // K3: windowed channel attention + gate
    k_attn<<<dim3(NWIN, HEADS), 128>>>(temp, mlp_w, mlp_b);

    // K4: projection (M=192, K=192) + bias -> d_out
    k_gemm<<<dim3(BATCH*HWSZ/128, CDIM/64), 128>>>(p_wtp, p_t, out, proj_b, 1, CDIM);
}